// round 1
// baseline (speedup 1.0000x reference)
#include <cuda_runtime.h>
#include <cuda_bf16.h>

// out[n,p,:] = feat[n,p,:] * mean_m task[n,m,p]
// n=32, m=16, p=1024, d=512 (fp32)
//
// One block per (n,p) row. 128 threads, one float4 each (512 floats).
// Mean over m computed redundantly per thread — uniform addresses per warp
// => broadcast loads, task (2 MiB) is L2-resident.

#define N_ 32
#define M_ 16
#define P_ 1024
#define D_ 512

__global__ __launch_bounds__(128, 16)
void MAP_20023137534634_kernel(const float* __restrict__ task,
                               const float* __restrict__ feat,
                               float* __restrict__ out) {
    const int row = blockIdx.x;            // n*P_ + p
    const int n = row >> 10;               // row / 1024
    const int p = row & (P_ - 1);          // row % 1024

    // Sum the 16 task values for this (n,p). Uniform per warp -> broadcast.
    const float* tbase = task + ((size_t)n * (M_ * P_) + p);
    float s = 0.0f;
#pragma unroll
    for (int m = 0; m < M_; ++m)
        s += __ldg(tbase + m * P_);
    const float mean = s * (1.0f / (float)M_);

    // Independent of the mean chain: issue the feat load early.
    const size_t base = (size_t)row * D_;
    const float4* f4 = reinterpret_cast<const float4*>(feat + base);
    float4*       o4 = reinterpret_cast<float4*>(out + base);

    float4 v = f4[threadIdx.x];
    v.x *= mean;
    v.y *= mean;
    v.z *= mean;
    v.w *= mean;
    o4[threadIdx.x] = v;
}

extern "C" void kernel_launch(void* const* d_in, const int* in_sizes, int n_in,
                              void* d_out, int out_size) {
    const float* task = (const float*)d_in[0];   // [32,16,1024]
    const float* feat = (const float*)d_in[1];   // [32,1024,512]
    float* out = (float*)d_out;                  // [32,1024,512]

    (void)in_sizes; (void)n_in; (void)out_size;

    MAP_20023137534634_kernel<<<N_ * P_, 128>>>(task, feat, out);
}

// round 2
// speedup vs baseline: 1.1128x; 1.1128x over previous
#include <cuda_runtime.h>
#include <cuda_bf16.h>

// out[n,p,:] = feat[n,p,:] * mean_m task[n,m,p]
// n=32, m=16, p=1024, d=512 (fp32)
//
// Two kernels:
//  1) mean_kernel: mean[n,p] = (1/16) * sum_m task[n,m,p], fully coalesced
//     float4 loads, one pass over task (2 MiB). mean (128 KiB) stays in L2.
//  2) scale_kernel: pure stream. Per warp: 1 broadcast mean load +
//     1 LDG.128 + 1 STG.128. DRAM-bound by design.

#define N_ 32
#define M_ 16
#define P_ 1024
#define D_ 512

__device__ float g_mean[N_ * P_];   // 128 KiB scratch (no runtime alloc)

// Grid: 32 blocks (one per n) x 256 threads; each thread handles 4 p via float4.
__global__ __launch_bounds__(256)
void mean_kernel(const float* __restrict__ task) {
    const int n = blockIdx.x;
    const int p4 = threadIdx.x;                     // float4 index, 0..255
    const float4* t4 = reinterpret_cast<const float4*>(task + (size_t)n * (M_ * P_));
    float4 s = make_float4(0.f, 0.f, 0.f, 0.f);
#pragma unroll
    for (int m = 0; m < M_; ++m) {
        float4 v = t4[m * (P_ / 4) + p4];
        s.x += v.x; s.y += v.y; s.z += v.z; s.w += v.w;
    }
    const float inv = 1.0f / (float)M_;
    s.x *= inv; s.y *= inv; s.z *= inv; s.w *= inv;
    reinterpret_cast<float4*>(g_mean + (size_t)n * P_)[p4] = s;
}

// Flat elementwise over 4.19M float4s. 256-thread blocks, 16384 blocks.
// Each warp stays inside one (n,p) row (row = 128 float4s), so the mean
// load is a uniform broadcast per warp.
__global__ __launch_bounds__(256)
void scale_kernel(const float* __restrict__ feat, float* __restrict__ out) {
    const size_t i = (size_t)blockIdx.x * blockDim.x + threadIdx.x; // float4 idx
    const int row = (int)(i >> 7);                  // / (D_/4)

    const float mean = __ldg(g_mean + row);         // warp-uniform broadcast

    const float4 v = reinterpret_cast<const float4*>(feat)[i];
    float4 r;
    r.x = v.x * mean;
    r.y = v.y * mean;
    r.z = v.z * mean;
    r.w = v.w * mean;
    reinterpret_cast<float4*>(out)[i] = r;
}

extern "C" void kernel_launch(void* const* d_in, const int* in_sizes, int n_in,
                              void* d_out, int out_size) {
    const float* task = (const float*)d_in[0];   // [32,16,1024]
    const float* feat = (const float*)d_in[1];   // [32,1024,512]
    float* out = (float*)d_out;                  // [32,1024,512]
    (void)in_sizes; (void)n_in; (void)out_size;

    mean_kernel<<<N_, 256>>>(task);

    const size_t total4 = (size_t)N_ * P_ * D_ / 4;   // 4,194,304
    scale_kernel<<<(unsigned)(total4 / 256), 256>>>(feat, out);
}

// round 3
// speedup vs baseline: 1.3195x; 1.1857x over previous
#include <cuda_runtime.h>
#include <cuda_bf16.h>

// out[n,p,:] = feat[n,p,:] * mean_m task[n,m,p]
// n=32, m=16, p=1024, d=512 (fp32)
//
// Kernel 1: mean[n,p] (flat, one scalar mean per thread, 16 coalesced loads).
// Kernel 2: streaming scale with 8 float4s per thread (MLP=8) + streaming
//           cache hints so feat/out don't evict mean from L2.

#define N_ 32
#define M_ 16
#define P_ 1024
#define D_ 512

#define UNROLL_ 8
#define TPB_ 256

__device__ float g_mean[N_ * P_];   // 128 KiB scratch

// 32768 means; 128 blocks x 256 threads, one mean each.
// For fixed m, consecutive threads read consecutive p -> coalesced.
__global__ __launch_bounds__(256)
void mean_kernel(const float* __restrict__ task) {
    const int idx = blockIdx.x * 256 + threadIdx.x;   // n*P_ + p
    const int n = idx >> 10;
    const int p = idx & (P_ - 1);
    const float* tb = task + (size_t)n * (M_ * P_) + p;
    float acc[M_];
#pragma unroll
    for (int m = 0; m < M_; ++m)
        acc[m] = __ldg(tb + m * P_);
    float s = 0.0f;
#pragma unroll
    for (int m = 0; m < M_; ++m)
        s += acc[m];
    g_mean[idx] = s * (1.0f / (float)M_);
}

// 4,194,304 float4s total. 2048 blocks x 256 threads x 8 float4s.
// Block covers 2048 consecutive float4s = 16 rows; iteration j is a
// fully-coalesced 4 KiB segment. Mean load per (thread, j) is a
// warp-uniform L2-hit broadcast.
__global__ __launch_bounds__(TPB_)
void scale_kernel(const float* __restrict__ feat, float* __restrict__ out) {
    const size_t base = (size_t)blockIdx.x * (TPB_ * UNROLL_) + threadIdx.x;
    const float4* f4 = reinterpret_cast<const float4*>(feat);
    float4*       o4 = reinterpret_cast<float4*>(out);

    float4 v[UNROLL_];
#pragma unroll
    for (int j = 0; j < UNROLL_; ++j)
        v[j] = __ldcs(f4 + base + (size_t)j * TPB_);     // MLP = 8

    float mu[UNROLL_];
#pragma unroll
    for (int j = 0; j < UNROLL_; ++j) {
        const size_t i = base + (size_t)j * TPB_;
        mu[j] = __ldg(g_mean + (int)(i >> 7));           // row = i / 128
    }

#pragma unroll
    for (int j = 0; j < UNROLL_; ++j) {
        float4 r;
        r.x = v[j].x * mu[j];
        r.y = v[j].y * mu[j];
        r.z = v[j].z * mu[j];
        r.w = v[j].w * mu[j];
        __stcs(o4 + base + (size_t)j * TPB_, r);
    }
}

extern "C" void kernel_launch(void* const* d_in, const int* in_sizes, int n_in,
                              void* d_out, int out_size) {
    const float* task = (const float*)d_in[0];   // [32,16,1024]
    const float* feat = (const float*)d_in[1];   // [32,1024,512]
    float* out = (float*)d_out;                  // [32,1024,512]
    (void)in_sizes; (void)n_in; (void)out_size;

    mean_kernel<<<(N_ * P_) / 256, 256>>>(task);

    const size_t total4 = (size_t)N_ * P_ * D_ / 4;            // 4,194,304
    const unsigned blocks = (unsigned)(total4 / (TPB_ * UNROLL_)); // 2048
    scale_kernel<<<blocks, TPB_>>>(feat, out);
}

// round 4
// speedup vs baseline: 1.4131x; 1.0709x over previous
#include <cuda_runtime.h>
#include <cuda_bf16.h>

// out[n,p,:] = feat[n,p,:] * mean_m task[n,m,p]
// n=32, m=16, p=1024, d=512 (fp32)
//
// Single fused kernel at the LTS roofline (~6.8 TB/s streaming cap):
//  - Each block owns 16 consecutive rows (same n): 2048 float4s.
//  - Prologue: 256 threads load the 16x16 task slab (one float each),
//    smem transpose-reduce -> 16 row means. Task read exactly once chip-wide.
//  - Main loop: 8 float4s/thread, streaming hints; mean via uniform LDS.

#define N_ 32
#define M_ 16
#define P_ 1024
#define D_ 512

#define UNROLL_ 8
#define TPB_ 256
#define ROWS_PER_BLK_ 16   // (TPB_*UNROLL_) / (D_/4)

__global__ __launch_bounds__(TPB_)
void MAP_fused_kernel(const float* __restrict__ task,
                      const float* __restrict__ feat,
                      float* __restrict__ out) {
    __shared__ float s_raw[ROWS_PER_BLK_ * 17];   // [pl][m], pad 17 vs conflicts
    __shared__ float s_mean[ROWS_PER_BLK_];

    const int tid = threadIdx.x;
    const int row0 = blockIdx.x * ROWS_PER_BLK_;       // global row = n*P_ + p
    const int n  = row0 >> 10;                         // all 16 rows share n
    const int p0 = row0 & (P_ - 1);

    // ---- prologue: 16 row means, one task element per thread ----
    {
        const int m  = tid >> 4;        // 0..15
        const int pl = tid & 15;        // 0..15
        const float v = __ldg(task + (size_t)n * (M_ * P_) + m * P_ + (p0 + pl));
        s_raw[pl * 17 + m] = v;
    }
    __syncthreads();
    if (tid < ROWS_PER_BLK_) {
        float s = 0.0f;
#pragma unroll
        for (int m = 0; m < M_; ++m)
            s += s_raw[tid * 17 + m];
        s_mean[tid] = s * (1.0f / (float)M_);
    }
    __syncthreads();

    // ---- streaming scale: 8 float4s per thread, fully coalesced ----
    const size_t base = (size_t)blockIdx.x * (TPB_ * UNROLL_) + tid;
    const float4* f4 = reinterpret_cast<const float4*>(feat);
    float4*       o4 = reinterpret_cast<float4*>(out);

    float4 v[UNROLL_];
#pragma unroll
    for (int j = 0; j < UNROLL_; ++j)
        v[j] = __ldcs(f4 + base + (size_t)j * TPB_);   // MLP = 8

#pragma unroll
    for (int j = 0; j < UNROLL_; ++j) {
        // local row index within block: warp-uniform -> LDS broadcast
        const int lrow = (int)(((size_t)j * TPB_ + tid) >> 7);  // /(D_/4)
        const float mu = s_mean[lrow];
        float4 r;
        r.x = v[j].x * mu;
        r.y = v[j].y * mu;
        r.z = v[j].z * mu;
        r.w = v[j].w * mu;
        __stcs(o4 + base + (size_t)j * TPB_, r);
    }
}

extern "C" void kernel_launch(void* const* d_in, const int* in_sizes, int n_in,
                              void* d_out, int out_size) {
    const float* task = (const float*)d_in[0];   // [32,16,1024]
    const float* feat = (const float*)d_in[1];   // [32,1024,512]
    float* out = (float*)d_out;                  // [32,1024,512]
    (void)in_sizes; (void)n_in; (void)out_size;

    const size_t total4 = (size_t)N_ * P_ * D_ / 4;               // 4,194,304
    const unsigned blocks = (unsigned)(total4 / (TPB_ * UNROLL_)); // 2048
    MAP_fused_kernel<<<blocks, TPB_>>>(task, feat, out);
}

// round 5
// speedup vs baseline: 1.5324x; 1.0845x over previous
#include <cuda_runtime.h>
#include <cuda_bf16.h>

// out[n,p,:] = feat[n,p,:] * mean_m task[n,m,p]
// n=32, m=16, p=1024, d=512 (fp32)
//
// Single fused kernel, warp-autonomous (no block barriers, no smem):
//  - Each warp owns 2 complete rows (2 x 128 float4s; 4 float4/thread/row).
//  - Row means: lanes 0-15 load row A's 16 task values, lanes 16-31 row B's;
//    shfl_xor segment-reduce (width 16) + 2 broadcasts. One task LDG/thread.
//  - feat loads issued before the shuffle chain to overlap task latency.

#define N_ 32
#define M_ 16
#define P_ 1024
#define D_ 512

#define TPB_ 256
#define ROWS_PER_BLK_ 16   // 8 warps x 2 rows

__global__ __launch_bounds__(TPB_)
void MAP_fused_kernel(const float* __restrict__ task,
                      const float* __restrict__ feat,
                      float* __restrict__ out) {
    const int tid  = threadIdx.x;
    const int warp = tid >> 5;
    const int lane = tid & 31;

    const int rowA = blockIdx.x * ROWS_PER_BLK_ + warp * 2;  // global row n*P_+p
    const int n  = rowA >> 10;           // same n for the whole block (16 | 1024)
    const int p0 = rowA & (P_ - 1);

    // ---- task load (issued first: feeds the shuffle chain) ----
    const int m = lane & 15;             // 0..15
    const int pr = p0 + (lane >> 4);     // row A for lanes 0-15, row B for 16-31
    float tv = __ldg(task + (size_t)n * (M_ * P_) + m * P_ + pr);

    // ---- feat loads (independent; overlap task latency) ----
    const float4* f4 = reinterpret_cast<const float4*>(feat);
    float4*       o4 = reinterpret_cast<float4*>(out);
    const size_t a = (size_t)rowA * (D_ / 4) + lane;   // row A, this lane
    float4 va[4], vb[4];
#pragma unroll
    for (int j = 0; j < 4; ++j)
        va[j] = __ldcs(f4 + a + j * 32);
#pragma unroll
    for (int j = 0; j < 4; ++j)
        vb[j] = __ldcs(f4 + a + (D_ / 4) + j * 32);

    // ---- segment reduce (width 16) -> both row means on every lane ----
    tv += __shfl_xor_sync(0xffffffffu, tv, 8, 16);
    tv += __shfl_xor_sync(0xffffffffu, tv, 4, 16);
    tv += __shfl_xor_sync(0xffffffffu, tv, 2, 16);
    tv += __shfl_xor_sync(0xffffffffu, tv, 1, 16);
    const float muA = __shfl_sync(0xffffffffu, tv, 0)  * (1.0f / (float)M_);
    const float muB = __shfl_sync(0xffffffffu, tv, 16) * (1.0f / (float)M_);

    // ---- scale + store ----
#pragma unroll
    for (int j = 0; j < 4; ++j) {
        float4 r;
        r.x = va[j].x * muA; r.y = va[j].y * muA;
        r.z = va[j].z * muA; r.w = va[j].w * muA;
        __stcs(o4 + a + j * 32, r);
    }
#pragma unroll
    for (int j = 0; j < 4; ++j) {
        float4 r;
        r.x = vb[j].x * muB; r.y = vb[j].y * muB;
        r.z = vb[j].z * muB; r.w = vb[j].w * muB;
        __stcs(o4 + a + (D_ / 4) + j * 32, r);
    }
}

extern "C" void kernel_launch(void* const* d_in, const int* in_sizes, int n_in,
                              void* d_out, int out_size) {
    const float* task = (const float*)d_in[0];   // [32,16,1024]
    const float* feat = (const float*)d_in[1];   // [32,1024,512]
    float* out = (float*)d_out;                  // [32,1024,512]
    (void)in_sizes; (void)n_in; (void)out_size;

    const unsigned blocks = (N_ * P_) / ROWS_PER_BLK_;   // 2048
    MAP_fused_kernel<<<blocks, TPB_>>>(task, feat, out);
}